// round 15
// baseline (speedup 1.0000x reference)
#include <cuda_runtime.h>
#include <cuda_bf16.h>

// Problem constants: x,y [4096, 16, 128] f32, out [4096, 99, 128] f32.
#define N_EDGES   4096
#define DIM_IN    16
#define DIM_OUT   99
#define VGROUPS   32               // 128 channels / 4 (float4), = warp width
#define NNZ_CAP   1024
#define NCHUNK    32               // bitmask chunks (NNZ_CAP/32)

#define MWARPS    10
#define MTHREADS  (MWARPS * 32)    // 320
#define MAXSLOTS  8
#define MAXITEMS  64

// Merged entries. .x: bit0 = reuse-a flag, bits[1..15] = mu1*512 (byte off),
//                     bits[16..31] = mu2*512 (byte off)
//                 .y = cg for row_lo, .z = cg for row_hi, .w unused
__device__ int4 g_ent[NNZ_CAP];
// Work items per (warp, slot): {ent_beg, ent_end, row_lo, row_hi}
//   row_lo = -1 : empty slot.  row_hi = -1 : single row (center, m3=0).
__device__ int4 g_work[MWARPS * MAXSLOTS];

__device__ __forceinline__ int blk_of(int m) {   // irrep block of input index
    return (m < 1) ? 0 : (m < 4) ? 1 : (m < 9) ? 2 : 3;
}

// Single-block deterministic build.
__global__ void build_kernel(const int* __restrict__ mu1,
                             const int* __restrict__ mu2,
                             const int* __restrict__ mu3,
                             const float* __restrict__ cg,
                             int nnz)
{
    __shared__ unsigned msk[DIM_OUT][NCHUNK];     // 12.7 KB
    __shared__ int      pref[DIM_OUT][NCHUNK];    // 12.7 KB
    __shared__ int      s_off[DIM_OUT + 1];
    __shared__ int      er1[NNZ_CAP];             // row-sorted mu1
    __shared__ int      er2[NNZ_CAP];             // row-sorted mu2
    __shared__ float    ecg[NNZ_CAP];             // row-sorted cg
    __shared__ int      row_gid[DIM_OUT];
    __shared__ int      it_lo[MAXITEMS], it_hi[MAXITEMS];
    __shared__ int      it_len[MAXITEMS], it_base[MAXITEMS];
    __shared__ int      s_nitems;

    const int tid = threadIdx.x;
    const int nt  = blockDim.x;

    for (int i = tid; i < DIM_OUT * NCHUNK; i += nt) (&msk[0][0])[i] = 0u;
    __syncthreads();

    // occupancy bitmasks (atomicOr: order-independent => deterministic)
    for (int j = tid; j < nnz; j += nt)
        atomicOr(&msk[mu3[j]][j >> 5], 1u << (j & 31));
    __syncthreads();

    // per-row chunk-prefix popcounts
    if (tid < DIM_OUT) {
        int acc = 0;
#pragma unroll
        for (int c = 0; c < NCHUNK; ++c) {
            pref[tid][c] = acc;
            acc += __popc(msk[tid][c]);
        }
        s_off[tid + 1] = acc;
    }
    if (tid == 0) s_off[0] = 0;
    __syncthreads();

    // parallel inclusive scan over s_off[1..99]  (=> s_off[k] = excl. offset of row k)
    for (int d = 1; d < 128; d <<= 1) {
        int v = 0;
        if (tid >= 1 && tid <= DIM_OUT && tid - d >= 1) v = s_off[tid - d];
        __syncthreads();
        if (tid >= 1 && tid <= DIM_OUT) s_off[tid] += v;
        __syncthreads();
    }

    // scatter into row-sorted arrays (rank via popcount)
    for (int j = tid; j < nnz; j += nt) {
        const int k = mu3[j];
        const int c = j >> 5, b = j & 31;
        const int rank = pref[k][c] + __popc(msk[k][c] & ((1u << b) - 1u));
        const int p = s_off[k] + rank;
        er1[p] = mu1[j];
        er2[p] = mu2[j];
        ecg[p] = cg[j];
    }
    __syncthreads();

    // per-row (l1,l2) group id from first entry
    if (tid < DIM_OUT) {
        const int off = s_off[tid];
        row_gid[tid] = (s_off[tid + 1] > off)
                     ? blk_of(er1[off]) * 4 + blk_of(er2[off]) : -1;
    }
    __syncthreads();

    // thread 0: split gid-runs into paths, emit partner-row work items
    if (tid == 0) {
        int np = 0, k = 0;
        while (k < DIM_OUT) {
            const int g = row_gid[k];
            int L = 0;
            while (k + L < DIM_OUT && row_gid[k + L] == g) ++L;
            int sizes[2]; int ns;
            if (L == 6)       { sizes[0] = 1; sizes[1] = 5; ns = 2; }
            else if (L == 10) { sizes[0] = 3; sizes[1] = 7; ns = 2; }
            else if (L == 4)  { sizes[0] = 1; sizes[1] = 3; ns = 2; }
            else if (L == 8)  { sizes[0] = 3; sizes[1] = 5; ns = 2; }
            else              { sizes[0] = L; ns = 1; }          // 1,3,5,7
            int kk = k;
            for (int i = 0; i < ns; ++i) {
                const int nr = sizes[i], l3 = (nr - 1) >> 1, k0 = kk;
                if (np < MAXITEMS) { it_lo[np] = k0 + l3; it_hi[np] = -1; ++np; }
                for (int d = 1; d <= l3 && np < MAXITEMS; ++d) {
                    it_lo[np] = k0 + l3 - d; it_hi[np] = k0 + l3 + d; ++np;
                }
                kk += nr;
            }
            k += L;
        }
        s_nitems = np;
    }
    __syncthreads();
    const int nitems = s_nitems;

    // merged length per item (two-pointer over sorted rows)
    if (tid < nitems) {
        const int lo = it_lo[tid], hi = it_hi[tid];
        int len;
        if (hi < 0) len = s_off[lo + 1] - s_off[lo];
        else {
            int i = s_off[lo], ie = s_off[lo + 1];
            int j2 = s_off[hi], je = s_off[hi + 1];
            len = 0;
            while (i < ie && j2 < je) {
                const int ka = er1[i] * 16 + er2[i];
                const int kb = er1[j2] * 16 + er2[j2];
                ++len;
                if (ka == kb) { ++i; ++j2; }
                else if (ka < kb) ++i;
                else ++j2;
            }
            len += (ie - i) + (je - j2);
        }
        it_len[tid] = len;
    }
    __syncthreads();

    // thread 0: bases + greedy deal (min-loaded warp), defaults for empties
    if (tid == 0) {
        int acc = 0;
        for (int i = 0; i < nitems; ++i) { it_base[i] = acc; acc += it_len[i]; }
        for (int s = 0; s < MWARPS * MAXSLOTS; ++s)
            g_work[s] = make_int4(0, 0, -1, -1);
        int wload[MWARPS], wcnt[MWARPS];
        for (int w = 0; w < MWARPS; ++w) { wload[w] = 0; wcnt[w] = 0; }
        for (int i = 0; i < nitems; ++i) {
            int best = -1, bl = 0x7fffffff;
            for (int w = 0; w < MWARPS; ++w)
                if (wcnt[w] < MAXSLOTS && wload[w] < bl) { bl = wload[w]; best = w; }
            if (best < 0) best = 0;
            g_work[best * MAXSLOTS + wcnt[best]] =
                make_int4(it_base[i], it_base[i] + it_len[i], it_lo[i], it_hi[i]);
            wload[best] += it_len[i];
            wcnt[best]  += 1;
        }
    }
    __syncthreads();

    // emit merged entries (per-row order preserved => reference summation order)
    if (tid < nitems) {
        const int lo = it_lo[tid], hi = it_hi[tid];
        int base = it_base[tid];
        int i = s_off[lo], ie = s_off[lo + 1];
        int prev = -1;
        if (hi < 0) {
            for (; i < ie; ++i) {
                const int m1 = er1[i];
                const int fl = (m1 == prev) ? 1 : 0;
                prev = m1;
                g_ent[base++] = make_int4((m1 * 512) | fl | ((er2[i] * 512) << 16),
                                          __float_as_int(ecg[i]), 0, 0);
            }
        } else {
            int j2 = s_off[hi], je = s_off[hi + 1];
            while (i < ie || j2 < je) {
                const int ka = (i  < ie) ? er1[i]  * 16 + er2[i]  : 0x7fffffff;
                const int kb = (j2 < je) ? er1[j2] * 16 + er2[j2] : 0x7fffffff;
                int m1, m2; float clo = 0.f, chi = 0.f;
                if (ka <= kb) {
                    m1 = er1[i]; m2 = er2[i]; clo = ecg[i]; ++i;
                    if (kb == ka) { chi = ecg[j2]; ++j2; }
                } else {
                    m1 = er1[j2]; m2 = er2[j2]; chi = ecg[j2]; ++j2;
                }
                const int fl = (m1 == prev) ? 1 : 0;
                prev = m1;
                g_ent[base++] = make_int4((m1 * 512) | fl | ((m2 * 512) << 16),
                                          __float_as_int(clo), __float_as_int(chi), 0);
            }
        }
    }
}

// Main kernel: one block per edge, 10 warps. Each warp processes work items
// (partner-row pairs / center singles); per merged entry one pair product
// feeds two register accumulators. Every output row is stored exactly once.
__global__ __launch_bounds__(MTHREADS)
void tp_main_kernel(const float4* __restrict__ x,
                    const float4* __restrict__ y,
                    float4* __restrict__ out)
{
    __shared__ float4 xs[DIM_IN * VGROUPS];   // 8 KB
    __shared__ float4 ys[DIM_IN * VGROUPS];   // 8 KB

    const int n    = blockIdx.x;
    const int tid  = threadIdx.x;
    const int w    = tid >> 5;
    const int lane = tid & 31;

    const float4* xb = x + (size_t)n * (DIM_IN * VGROUPS);
    const float4* yb = y + (size_t)n * (DIM_IN * VGROUPS);
#pragma unroll
    for (int i = tid; i < DIM_IN * VGROUPS; i += MTHREADS) {
        xs[i] = xb[i];
        ys[i] = yb[i];
    }
    __syncthreads();

    const char* xc = (const char*)xs + lane * 16;
    const char* yc = (const char*)ys + lane * 16;

    float4* ob = out + (size_t)n * (DIM_OUT * VGROUPS) + lane;

#pragma unroll
    for (int slot = 0; slot < MAXSLOTS; ++slot) {
        const int4 wk = __ldg(&g_work[w * MAXSLOTS + slot]);
        if (wk.z < 0) continue;
        const int beg = wk.x, end = wk.y, klo = wk.z, khi = wk.w;

        float4 acc_lo = make_float4(0.f, 0.f, 0.f, 0.f);
        float4 acc_hi = acc_lo;
        float4 a      = acc_lo;

#pragma unroll 4
        for (int j = beg; j < end; ++j) {
            const int4 e = __ldg(&g_ent[j]);          // uniform broadcast, L1-hot
            if (!(e.x & 1))                           // warp-uniform reuse flag
                a = *(const float4*)(xc + (e.x & 0xfffe));
            const float4 b = *(const float4*)(yc + ((unsigned)e.x >> 16));
            float4 p;
            p.x = a.x * b.x; p.y = a.y * b.y;
            p.z = a.z * b.z; p.w = a.w * b.w;
            const float clo = __int_as_float(e.y);
            const float chi = __int_as_float(e.z);
            acc_lo.x = fmaf(clo, p.x, acc_lo.x);
            acc_lo.y = fmaf(clo, p.y, acc_lo.y);
            acc_lo.z = fmaf(clo, p.z, acc_lo.z);
            acc_lo.w = fmaf(clo, p.w, acc_lo.w);
            acc_hi.x = fmaf(chi, p.x, acc_hi.x);
            acc_hi.y = fmaf(chi, p.y, acc_hi.y);
            acc_hi.z = fmaf(chi, p.z, acc_hi.z);
            acc_hi.w = fmaf(chi, p.w, acc_hi.w);
        }

        ob[(size_t)klo * VGROUPS] = acc_lo;
        if (khi >= 0) ob[(size_t)khi * VGROUPS] = acc_hi;
    }
}

extern "C" void kernel_launch(void* const* d_in, const int* in_sizes, int n_in,
                              void* d_out, int out_size)
{
    const float* x   = (const float*)d_in[0];
    const float* y   = (const float*)d_in[1];
    const int*   mu1 = (const int*)  d_in[2];
    const int*   mu2 = (const int*)  d_in[3];
    const int*   mu3 = (const int*)  d_in[4];
    const float* cg  = (const float*)d_in[5];

    int nnz = in_sizes[5];
    if (nnz > NNZ_CAP) nnz = NNZ_CAP;

    build_kernel<<<1, 1024>>>(mu1, mu2, mu3, cg, nnz);

    tp_main_kernel<<<N_EDGES, MTHREADS>>>((const float4*)x,
                                          (const float4*)y,
                                          (float4*)d_out);
}